// round 16
// baseline (speedup 1.0000x reference)
#include <cuda_runtime.h>
#include <cuda_fp16.h>
#include <cstdint>

#define Bq 8
#define Hh 256
#define Ww 256
#define CINc 64
#define COUTc 64
#define STYLE_INc 512

// ---------------------------------------------------------------------------
// scratch (no allocs allowed)
// ---------------------------------------------------------------------------
__device__ float g_s[Bq * CINc];
// B operand, fp16: [b][h(2)][dy(3)][dx(3)] blocks of [co(64)][ci(32)] halves
__device__ __half g_wBh[Bq * 2 * 3 * 3 * 2048];

// ---------------------------------------------------------------------------
// Kernel 1: style modulation (split-K)
// ---------------------------------------------------------------------------
__global__ void k_style(const float* __restrict__ style,
                        const float* __restrict__ mw,
                        const float* __restrict__ mb) {
    const int b  = blockIdx.x;
    const int ci = threadIdx.x & 63;
    const int kp = threadIdx.x >> 6;
    const float scale = 0.04419417382415922f;   // 1/sqrt(512)
    const float* st = style + b * STYLE_INc;
    float acc = 0.f;
    const int k0 = kp * 64;
#pragma unroll 8
    for (int k = k0; k < k0 + 64; ++k)
        acc += st[k] * mw[k * CINc + ci];
    __shared__ float red[512];
    red[threadIdx.x] = acc;
    __syncthreads();
    if (kp == 0) {
        float s = 0.f;
#pragma unroll
        for (int j = 0; j < 8; ++j) s += red[j * 64 + ci];
        g_s[b * CINc + ci] = s * scale + mb[ci];
    }
}

// ---------------------------------------------------------------------------
// Kernel 2: modulate + demodulate, emit fp16 B blocks [co][ci32]
// grid (COUT, B), 64 threads (ci)
// ---------------------------------------------------------------------------
__global__ void k_modw(const float* __restrict__ weight) {
    int co = blockIdx.x;
    int b  = blockIdx.y;
    int ci = threadIdx.x;
    const float cscale = 1.0f / 24.0f;   // 1/sqrt(64*9)
    float sv = g_s[b * CINc + ci];
    const float* wp = weight + (co * CINc + ci) * 9;
    float v[9];
    float ssum = 0.f;
#pragma unroll
    for (int k = 0; k < 9; ++k) {
        v[k] = cscale * wp[k] * sv;
        ssum += v[k] * v[k];
    }
#pragma unroll
    for (int off = 16; off > 0; off >>= 1)
        ssum += __shfl_xor_sync(0xffffffffu, ssum, off);
    __shared__ float red[2];
    if ((ci & 31) == 0) red[ci >> 5] = ssum;
    __syncthreads();
    float demod = rsqrtf(red[0] + red[1] + 1e-8f);
    const int h = ci >> 5;
#pragma unroll
    for (int k = 0; k < 9; ++k) {
        int dy = k / 3, dx = k - 3 * dy;
        unsigned blk = (((b * 2 + h) * 3 + dy) * 3 + dx) * 2048u;
        g_wBh[blk + co * 32 + (ci & 31)] = __float2half_rn(v[k] * demod);
    }
}

// ---------------------------------------------------------------------------
// Kernel 3: implicit-GEMM conv, mma.sync.m16n8k16 fp16 (f32 accum).
// CTA = (x-half, y, b): M=128 px, N=64, K=576. 6 stages (2 ci-halves x 3 dy);
// each stage = 3 dx taps x 2 k16-chunks.
// 8 warps = 4 m-warps (32 px) x 2 n-warps (32 co); warp tile m32 x n32.
// Occupancy-first: no register prefetch, 2 CTAs/SM hide staging latency.
// ---------------------------------------------------------------------------
#define APITCH 20                 // u32 words per pixel/co row (80B, conflict-free)
#define A_WORDS (130 * APITCH)    // 2600
#define B_WORDS (3 * 64 * APITCH) // 3840

__global__ __launch_bounds__(256, 2)
void k_conv(const float* __restrict__ in, float* __restrict__ out) {
    __shared__ __align__(16) unsigned sA[A_WORDS];   // [px(130)][ci16x2] pitch 20
    __shared__ __align__(16) unsigned sB[B_WORDS];   // [dx(3)][co(64)][ci16x2] pitch 20

    const int x0 = blockIdx.x * 128;
    const int y  = blockIdx.y;
    const int b  = blockIdx.z;
    const int tid = threadIdx.x;
    const int wid = tid >> 5;
    const int lane = tid & 31;
    const int wr = wid >> 1;          // m-warp: pixels wr*32..+31
    const int wc = wid & 1;           // n-warp: couts wc*32..+31
    const int r4 = lane >> 2;         // 0..7
    const int c4 = lane & 3;          // 0..3

    float acc[2][4][4];
#pragma unroll
    for (int mi = 0; mi < 2; ++mi)
#pragma unroll
        for (int ni = 0; ni < 4; ++ni)
#pragma unroll
            for (int j = 0; j < 4; ++j) acc[mi][ni][j] = 0.f;

    const float* inb = in + (size_t)b * Hh * Ww * CINc;

    for (int s = 0; s < 6; ++s) {
        const int h  = s / 3;
        const int dy = s - 3 * h;
        const int y_in = y + dy - 1;
        const bool rowok = (unsigned)y_in < (unsigned)Hh;

        __syncthreads();
        // ---- stage A: 130 px x 32 ci, fp32 LDG -> fp16 STS ----
#pragma unroll
        for (int k = 0; k < 5; ++k) {
            int idx = tid + k * 256;
            if (idx < 1040) {
                int p = idx >> 3, f = idx & 7;
                float4 v = make_float4(0.f, 0.f, 0.f, 0.f);
                int gx = x0 - 1 + p;
                if (rowok && (unsigned)gx < (unsigned)Ww)
                    v = *(const float4*)(inb +
                        ((size_t)(y_in * Ww + gx) * CINc) + h * 32 + f * 4);
                __half2 h0 = __floats2half2_rn(v.x, v.y);
                __half2 h1 = __floats2half2_rn(v.z, v.w);
                uint2 w;
                w.x = *(unsigned*)&h0;
                w.y = *(unsigned*)&h1;
                *(uint2*)(sA + p * APITCH + f * 2) = w;
            }
        }
        // ---- stage B: 3 dx taps x [64 co x 32 ci] fp16 = 768 uint4 ----
        {
            const uint4* bsrc = (const uint4*)(g_wBh +
                (size_t)(((b * 2 + h) * 3 + dy) * 3) * 2048);
#pragma unroll
            for (int j = 0; j < 3; ++j) {
                int i = tid + j * 256;      // < 768
                uint4 v = bsrc[i];
                int tap = i >> 8;           // 0..2 (256 uint4 per tap)
                int rm  = i & 255;          // co*4 + f
                int co  = rm >> 2, f = rm & 3;
                *(uint4*)(sB + (tap * 64 + co) * APITCH + f * 4) = v;
            }
        }
        __syncthreads();

        // ---- mma over 3 dx taps x 2 k16-chunks ----
#pragma unroll
        for (int dx = 0; dx < 3; ++dx) {
            const unsigned* Ap = sA + (wr * 32 + dx) * APITCH;
            const unsigned* Bp = sB + (dx * 64 + wc * 32) * APITCH;
#pragma unroll
            for (int kk = 0; kk < 2; ++kk) {
                const int kc = kk * 8 + c4;
                unsigned a[2][4];
#pragma unroll
                for (int mi = 0; mi < 2; ++mi) {
                    const unsigned* ap = Ap + (mi * 16 + r4) * APITCH + kc;
                    a[mi][0] = ap[0];
                    a[mi][1] = ap[8 * APITCH];
                    a[mi][2] = ap[4];
                    a[mi][3] = ap[8 * APITCH + 4];
                }
                unsigned bfr[4][2];
#pragma unroll
                for (int ni = 0; ni < 4; ++ni) {
                    const unsigned* bp = Bp + (ni * 8 + r4) * APITCH + kc;
                    bfr[ni][0] = bp[0];
                    bfr[ni][1] = bp[4];
                }
#pragma unroll
                for (int mi = 0; mi < 2; ++mi)
#pragma unroll
                    for (int ni = 0; ni < 4; ++ni) {
                        asm volatile(
                            "mma.sync.aligned.m16n8k16.row.col.f32.f16.f16.f32 "
                            "{%0,%1,%2,%3}, {%4,%5,%6,%7}, {%8,%9}, {%0,%1,%2,%3};"
                            : "+f"(acc[mi][ni][0]), "+f"(acc[mi][ni][1]),
                              "+f"(acc[mi][ni][2]), "+f"(acc[mi][ni][3])
                            : "r"(a[mi][0]), "r"(a[mi][1]), "r"(a[mi][2]), "r"(a[mi][3]),
                              "r"(bfr[ni][0]), "r"(bfr[ni][1]));
                    }
            }
        }
    }

    // epilogue: c0,c1 -> (px r4, cols 2c4..2c4+1); c2,c3 -> px r4+8
#pragma unroll
    for (int mi = 0; mi < 2; ++mi) {
        const int px0 = x0 + wr * 32 + mi * 16 + r4;
        float* op0 = out + (((size_t)b * Hh + y) * Ww + px0) * COUTc;
        float* op1 = op0 + 8 * (size_t)COUTc;   // pixel +8
#pragma unroll
        for (int ni = 0; ni < 4; ++ni) {
            const int co = wc * 32 + ni * 8 + 2 * c4;
            *(float2*)(op0 + co) = make_float2(acc[mi][ni][0], acc[mi][ni][1]);
            *(float2*)(op1 + co) = make_float2(acc[mi][ni][2], acc[mi][ni][3]);
        }
    }
}

// ---------------------------------------------------------------------------
extern "C" void kernel_launch(void* const* d_in, const int* in_sizes, int n_in,
                              void* d_out, int out_size) {
    const float* inputs     = (const float*)d_in[0];   // [8,256,256,64]
    const float* style      = (const float*)d_in[1];   // [8,512]
    const float* mod_weight = (const float*)d_in[2];   // [512,64]
    const float* mod_bias   = (const float*)d_in[3];   // [64]
    const float* weight     = (const float*)d_in[4];   // [1,64,64,3,3]
    float* out = (float*)d_out;

    k_style<<<8, 512>>>(style, mod_weight, mod_bias);
    k_modw<<<dim3(COUTc, Bq), 64>>>(weight);
    k_conv<<<dim3(Ww / 128, Hh, Bq), 256>>>(inputs, out);
}

// round 17
// speedup vs baseline: 1.1609x; 1.1609x over previous
#include <cuda_runtime.h>
#include <cuda_fp16.h>
#include <cstdint>

#define Bq 8
#define Hh 256
#define Ww 256
#define CINc 64
#define COUTc 64
#define STYLE_INc 512

// ---------------------------------------------------------------------------
// scratch (no allocs allowed)
// ---------------------------------------------------------------------------
__device__ float g_s[Bq * CINc];
// B operand, fp16: [b][h(2)][dy(3)][dx(3)] blocks of [co(64)][ci(32)] halves
__device__ __half g_wBh[Bq * 2 * 3 * 3 * 2048];

__device__ __forceinline__ uint32_t smem_u32(const void* p) {
    uint32_t a;
    asm("{ .reg .u64 t; cvta.to.shared.u64 t, %1; cvt.u32.u64 %0, t; }"
        : "=r"(a) : "l"(p));
    return a;
}

// ---------------------------------------------------------------------------
// Kernel 1: style modulation (split-K)
// ---------------------------------------------------------------------------
__global__ void k_style(const float* __restrict__ style,
                        const float* __restrict__ mw,
                        const float* __restrict__ mb) {
    const int b  = blockIdx.x;
    const int ci = threadIdx.x & 63;
    const int kp = threadIdx.x >> 6;
    const float scale = 0.04419417382415922f;   // 1/sqrt(512)
    const float* st = style + b * STYLE_INc;
    float acc = 0.f;
    const int k0 = kp * 64;
#pragma unroll 8
    for (int k = k0; k < k0 + 64; ++k)
        acc += st[k] * mw[k * CINc + ci];
    __shared__ float red[512];
    red[threadIdx.x] = acc;
    __syncthreads();
    if (kp == 0) {
        float s = 0.f;
#pragma unroll
        for (int j = 0; j < 8; ++j) s += red[j * 64 + ci];
        g_s[b * CINc + ci] = s * scale + mb[ci];
    }
}

// ---------------------------------------------------------------------------
// Kernel 2: modulate + demodulate, emit fp16 B blocks [co][ci32]
// grid (COUT, B), 64 threads (ci)
// ---------------------------------------------------------------------------
__global__ void k_modw(const float* __restrict__ weight) {
    int co = blockIdx.x;
    int b  = blockIdx.y;
    int ci = threadIdx.x;
    const float cscale = 1.0f / 24.0f;   // 1/sqrt(64*9)
    float sv = g_s[b * CINc + ci];
    const float* wp = weight + (co * CINc + ci) * 9;
    float v[9];
    float ssum = 0.f;
#pragma unroll
    for (int k = 0; k < 9; ++k) {
        v[k] = cscale * wp[k] * sv;
        ssum += v[k] * v[k];
    }
#pragma unroll
    for (int off = 16; off > 0; off >>= 1)
        ssum += __shfl_xor_sync(0xffffffffu, ssum, off);
    __shared__ float red[2];
    if ((ci & 31) == 0) red[ci >> 5] = ssum;
    __syncthreads();
    float demod = rsqrtf(red[0] + red[1] + 1e-8f);
    const int h = ci >> 5;
#pragma unroll
    for (int k = 0; k < 9; ++k) {
        int dy = k / 3, dx = k - 3 * dy;
        unsigned blk = (((b * 2 + h) * 3 + dy) * 3 + dx) * 2048u;
        g_wBh[blk + co * 32 + (ci & 31)] = __float2half_rn(v[k] * demod);
    }
}

// ---------------------------------------------------------------------------
// Kernel 3: implicit-GEMM conv, mma.sync.m16n8k16 fp16 (f32 accum).
// CTA = (x-half, y-pair, b): M=256 (2 rows x 128 px), N=64, K=576.
// 6 stages (2 ci-halves x 3 dy), each = 3 dx x 2 k16-chunks.
// 8 warps = (row, x-quarter, n-half); warp tile m64 x n32.
// ldmatrix fragment loads + double-buffered smem (1 sync/stage) +
// register LDG prefetch of stage s+1 under mma of stage s.
// ---------------------------------------------------------------------------
#define APITCH 20                    // u32 words per pixel/co row (80B)
#define A_WORDS (2 * 130 * APITCH)   // 5200
#define B_WORDS (3 * 64 * APITCH)    // 3840
#define BUF_WORDS (A_WORDS + B_WORDS)            // 9040
#define SMEM_BYTES (2 * BUF_WORDS * 4)           // 72320

__global__ __launch_bounds__(256)
void k_conv(const float* __restrict__ in, float* __restrict__ out) {
    extern __shared__ __align__(16) unsigned dynsm[];

    const int x0 = blockIdx.x * 128;
    const int y0 = blockIdx.y * 2;
    const int b  = blockIdx.z;
    const int tid = threadIdx.x;
    const int wid = tid >> 5;
    const int lane = tid & 31;
    const int rr   = wid >> 2;               // output row within pair (0/1)
    const int xoff = ((wid >> 1) & 1) * 64;  // x-quarter base
    const int wc   = wid & 1;                // n-warp: couts wc*32..+31
    const int r4 = lane >> 2;                // 0..7
    const int c4 = lane & 3;                 // 0..3

    const uint32_t smbase = smem_u32(dynsm);
    // per-lane invariant ldmatrix offsets (bytes)
    const uint32_t laneA = (uint32_t)((lane & 15) * 80 + (lane >> 4) * 16);
    const int ll = lane & 15;
    const uint32_t laneB = (uint32_t)((ll & 7) * 80 + (ll >> 3) * 16);

    float acc[4][4][4];
#pragma unroll
    for (int mi = 0; mi < 4; ++mi)
#pragma unroll
        for (int ni = 0; ni < 4; ++ni)
#pragma unroll
            for (int j = 0; j < 4; ++j) acc[mi][ni][j] = 0.f;

    const float* inb = in + (size_t)b * Hh * Ww * CINc;

    float4 rAf[9];
    uint4  rB[3];

#define LDG_STAGE(hh, dyy)                                                     \
    {                                                                          \
        _Pragma("unroll")                                                      \
        for (int k = 0; k < 9; ++k) {                                          \
            int idx = tid + k * 256;                                           \
            float4 v = make_float4(0.f, 0.f, 0.f, 0.f);                        \
            if (idx < 2080) {                                                  \
                int r   = (idx >= 1040) ? 1 : 0;                               \
                int rem = idx - r * 1040;                                      \
                int p   = rem >> 3, f = rem & 7;                               \
                int in_r = y0 + (dyy)-1 + r;                                   \
                int gx   = x0 - 1 + p;                                         \
                if ((unsigned)in_r < (unsigned)Hh && (unsigned)gx < (unsigned)Ww) \
                    v = *(const float4*)(inb +                                 \
                        ((size_t)(in_r * Ww + gx) * CINc) + (hh)*32 + f * 4);  \
            }                                                                  \
            rAf[k] = v;                                                        \
        }                                                                      \
        const uint4* bsrc = (const uint4*)(g_wBh +                             \
            (size_t)(((b * 2 + (hh)) * 3 + (dyy)) * 3) * 2048);                \
        _Pragma("unroll")                                                      \
        for (int j = 0; j < 3; ++j) rB[j] = bsrc[tid + j * 256];               \
    }

#define STS_STAGE(bufbase)                                                     \
    {                                                                          \
        unsigned* sA = (bufbase);                                              \
        unsigned* sB = (bufbase) + A_WORDS;                                    \
        _Pragma("unroll")                                                      \
        for (int k = 0; k < 9; ++k) {                                          \
            int idx = tid + k * 256;                                           \
            if (idx < 2080) {                                                  \
                int r   = (idx >= 1040) ? 1 : 0;                               \
                int rem = idx - r * 1040;                                      \
                int p   = rem >> 3, f = rem & 7;                               \
                __half2 h0 = __floats2half2_rn(rAf[k].x, rAf[k].y);            \
                __half2 h1 = __floats2half2_rn(rAf[k].z, rAf[k].w);            \
                uint2 w;                                                       \
                w.x = *(unsigned*)&h0;                                         \
                w.y = *(unsigned*)&h1;                                         \
                *(uint2*)(sA + (r * 130 + p) * APITCH + f * 2) = w;            \
            }                                                                  \
        }                                                                      \
        _Pragma("unroll")                                                      \
        for (int j = 0; j < 3; ++j) {                                          \
            int i = tid + j * 256;                                             \
            int tap = i >> 8;                                                  \
            int rm  = i & 255;                                                 \
            int co  = rm >> 2, f = rm & 3;                                     \
            *(uint4*)(sB + (tap * 64 + co) * APITCH + f * 4) = rB[j];          \
        }                                                                      \
    }

    LDG_STAGE(0, 0);
    STS_STAGE(dynsm);
    __syncthreads();

    for (int s = 0; s < 6; ++s) {
        // prefetch next stage into registers (hidden under mma below)
        if (s < 5) {
            int s1 = s + 1;
            int h1 = s1 / 3, dy1 = s1 - 3 * h1;
            LDG_STAGE(h1, dy1);
        }

        // ---- mma on buffer s&1 ----
        const uint32_t sAaddr = smbase + (uint32_t)(s & 1) * (BUF_WORDS * 4);
        const uint32_t sBaddr = sAaddr + A_WORDS * 4;
#pragma unroll
        for (int dx = 0; dx < 3; ++dx) {
            const uint32_t abase = sAaddr +
                (uint32_t)((rr * 130 + xoff + dx) * 80);
            const uint32_t bbase = sBaddr +
                (uint32_t)((dx * 64 + wc * 32) * 80);
#pragma unroll
            for (int kk = 0; kk < 2; ++kk) {
                unsigned a[4][4];
#pragma unroll
                for (int mi = 0; mi < 4; ++mi) {
                    uint32_t ad = abase + (uint32_t)(mi * 16 * 80 + kk * 32) + laneA;
                    asm volatile(
                        "ldmatrix.sync.aligned.m8n8.x4.shared.b16 "
                        "{%0,%1,%2,%3}, [%4];"
                        : "=r"(a[mi][0]), "=r"(a[mi][1]),
                          "=r"(a[mi][2]), "=r"(a[mi][3])
                        : "r"(ad));
                }
                unsigned bfr[4][2];
#pragma unroll
                for (int ni = 0; ni < 4; ++ni) {
                    uint32_t bd = bbase + (uint32_t)(ni * 8 * 80 + kk * 32) + laneB;
                    asm volatile(
                        "ldmatrix.sync.aligned.m8n8.x2.shared.b16 "
                        "{%0,%1}, [%2];"
                        : "=r"(bfr[ni][0]), "=r"(bfr[ni][1])
                        : "r"(bd));
                }
#pragma unroll
                for (int mi = 0; mi < 4; ++mi)
#pragma unroll
                    for (int ni = 0; ni < 4; ++ni) {
                        asm volatile(
                            "mma.sync.aligned.m16n8k16.row.col.f32.f16.f16.f32 "
                            "{%0,%1,%2,%3}, {%4,%5,%6,%7}, {%8,%9}, {%0,%1,%2,%3};"
                            : "+f"(acc[mi][ni][0]), "+f"(acc[mi][ni][1]),
                              "+f"(acc[mi][ni][2]), "+f"(acc[mi][ni][3])
                            : "r"(a[mi][0]), "r"(a[mi][1]),
                              "r"(a[mi][2]), "r"(a[mi][3]),
                              "r"(bfr[ni][0]), "r"(bfr[ni][1]));
                    }
            }
        }

        // ---- STS next stage into the other buffer ----
        if (s < 5) {
            STS_STAGE(dynsm + ((s + 1) & 1) * BUF_WORDS);
        }
        __syncthreads();
    }

    // epilogue: c0,c1 -> (px r4, cols 2c4..2c4+1); c2,c3 -> px r4+8
    const int y = y0 + rr;
#pragma unroll
    for (int mi = 0; mi < 4; ++mi) {
        const int px0 = x0 + xoff + mi * 16 + r4;
        float* op0 = out + (((size_t)b * Hh + y) * Ww + px0) * COUTc;
        float* op1 = op0 + 8 * (size_t)COUTc;   // pixel +8
#pragma unroll
        for (int ni = 0; ni < 4; ++ni) {
            const int co = wc * 32 + ni * 8 + 2 * c4;
            *(float2*)(op0 + co) = make_float2(acc[mi][ni][0], acc[mi][ni][1]);
            *(float2*)(op1 + co) = make_float2(acc[mi][ni][2], acc[mi][ni][3]);
        }
    }
}

// ---------------------------------------------------------------------------
extern "C" void kernel_launch(void* const* d_in, const int* in_sizes, int n_in,
                              void* d_out, int out_size) {
    const float* inputs     = (const float*)d_in[0];   // [8,256,256,64]
    const float* style      = (const float*)d_in[1];   // [8,512]
    const float* mod_weight = (const float*)d_in[2];   // [512,64]
    const float* mod_bias   = (const float*)d_in[3];   // [64]
    const float* weight     = (const float*)d_in[4];   // [1,64,64,3,3]
    float* out = (float*)d_out;

    cudaFuncSetAttribute(k_conv, cudaFuncAttributeMaxDynamicSharedMemorySize,
                         SMEM_BYTES);

    k_style<<<8, 512>>>(style, mod_weight, mod_bias);
    k_modw<<<dim3(COUTc, Bq), 64>>>(weight);
    k_conv<<<dim3(Ww / 128, Hh / 2, Bq), 256, SMEM_BYTES>>>(inputs, out);
}